// round 15
// baseline (speedup 1.0000x reference)
#include <cuda_runtime.h>
#include <math.h>

#define H      128
#define EVT    4096
#define NN     20000
#define NE     320000
#define MAXN   100000
#define MAXE   300000
#define MSG    640
#define DSTBIT (1 << 30)

// ------------------- device scratch (static, allowed) -------------------
__device__ float    g_aggS[MAXN * MSG];
__device__ float    g_aggD[MAXN * MSG];
__device__ float    g_cntS[MAXN];
__device__ float    g_cntD[MAXN];
__device__ float    g_Hst [2 * EVT * H];
__device__ float    g_GI  [2 * EVT * 384];
__device__ float    g_GH  [2 * EVT * 384];
__device__ float    g_newMem[2 * EVT * H];
__device__ int      g_tag [MAXN];        // 0-init; monotone atomicMax keys
// unique-edge machinery
__device__ int      g_flag[MAXE];        // 0-init; cleared at end of each launch
__device__ int      g_list[MAXE];
__device__ int      g_slot[MAXE];
__device__ int      g_ucount;            // 0-init; reset at end of each launch
__device__ float    g_urelt[MAXE];
__device__ float    g_Ec  [MAXE * H];
__device__ float    g_qkvs[NN * 512];    // [q | k | v | skip]
// dst-sorted edge machinery
__device__ int      g_cnt [NN];
__device__ int      g_off [NN + 1];
__device__ int      g_cur [NN];
__device__ int      g_ss  [NE];          // src, sorted by dst
__device__ int      g_su  [NE];          // unique-eid slot, sorted by dst
// weights
__device__ float    g_wihT[640 * 384];
__device__ float    g_whhT[128 * 384];
__device__ float    g_weT [256 * 128];
__device__ float    g_wcT [128 * 512];
__device__ float    g_bc  [512];

// ------------------- helpers -------------------
__device__ __forceinline__ float get_time(const void* p) {
    int iv = *(const int*)p;
    if (iv > -1000000 && iv < 1000000) return (float)iv;
    return *(const float*)p;
}
__device__ __forceinline__ unsigned f2tf32(float f) {
    unsigned r;
    asm("cvt.rna.tf32.f32 %0, %1;" : "=r"(r) : "f"(f));
    return r;
}
__device__ __forceinline__ void mma_tf32(float* d, const unsigned* a, const unsigned* b) {
    asm("mma.sync.aligned.m16n8k8.row.col.f32.tf32.tf32.f32 "
        "{%0,%1,%2,%3}, {%4,%5,%6,%7}, {%8,%9}, {%0,%1,%2,%3};"
        : "+f"(d[0]), "+f"(d[1]), "+f"(d[2]), "+f"(d[3])
        : "r"(a[0]), "r"(a[1]), "r"(a[2]), "r"(a[3]), "r"(b[0]), "r"(b[1]));
}

// ------------------- K1: fused prep (all independent) -------------------
// [0,960) wihT | [960,1152) whhT | [1152,1280) weT | [1280,1536) packw
// [1536,2786) flag | [2786,2865) cnt0 | [2865,6961) zero | [6961,11057) Hst
__global__ void __launch_bounds__(256) k_prep(
    const float* __restrict__ gru_w_ih, const float* __restrict__ gru_w_hh,
    const float* __restrict__ we,
    const float* __restrict__ wq, const float* __restrict__ wk,
    const float* __restrict__ wv, const float* __restrict__ ws,
    const float* __restrict__ bq, const float* __restrict__ bk,
    const float* __restrict__ bv, const float* __restrict__ bs,
    const int* __restrict__ eids,
    const int* __restrict__ sids, const int* __restrict__ dids,
    const float* __restrict__ memory)
{
    int b = blockIdx.x, tid = threadIdx.x;
    if (b < 960) {
        int o = b * 256 + tid;
        int k = o / 384, n = o % 384;
        g_wihT[o] = gru_w_ih[n * 640 + k];
    } else if (b < 1152) {
        int o = (b - 960) * 256 + tid;
        int k = o / 384, n = o % 384;
        g_whhT[o] = gru_w_hh[n * 128 + k];
    } else if (b < 1280) {
        int o = (b - 1152) * 256 + tid;
        int k = o / 128, n = o % 128;
        g_weT[o] = we[n * 256 + k];
    } else if (b < 1536) {
        int o = (b - 1280) * 256 + tid;
        int k = o >> 9, n = o & 511;
        int grp = n >> 7, r = n & 127;
        const float* w = (grp == 0) ? wq : (grp == 1) ? wk : (grp == 2) ? wv : ws;
        g_wcT[o] = w[r * 128 + k];
        if (k == 0) {
            const float* bb = (grp == 0) ? bq : (grp == 1) ? bk : (grp == 2) ? bv : bs;
            g_bc[n] = bb[r];
        }
    } else if (b < 2786) {
        int j = (b - 1536) * 256 + tid;
        if (j < NE) {
            int e = eids[j];
            if (atomicExch(&g_flag[e], 1) == 0) {
                int u = atomicAdd(&g_ucount, 1);
                g_list[u] = e;
                g_slot[e] = u;
            }
        }
    } else if (b < 2865) {
        int i = (b - 2786) * 256 + tid;
        if (i < NN) g_cnt[i] = 0;
    } else if (b < 6961) {
        int i = b - 2865;
        int sid = sids[i], did = dids[i];
        for (int t = tid; t < MSG; t += 256) {
            g_aggS[sid * MSG + t] = 0.f;
            g_aggD[did * MSG + t] = 0.f;
        }
        if (tid == 0) { g_cntS[sid] = 0.f; g_cntD[did] = 0.f; }
    } else {
        int rr = (b - 6961) * 2 + (tid >> 7);   // row in [0, 2*EVT)
        int h = tid & 127;
        bool isS = rr < EVT;
        int i = isS ? rr : rr - EVT;
        int id = isS ? sids[i] : dids[i];
        g_Hst[rr * H + h] = memory[id * H + h];
    }
}

// ------------------- K2: msg + hist + urelt -------------------
__global__ void __launch_bounds__(256) k_phase2(
    const int* __restrict__ et, const int* __restrict__ sids,
    const float* __restrict__ smask, const int* __restrict__ dids,
    const float* __restrict__ dmask, const int* __restrict__ eids,
    const float* __restrict__ eemb, const float* __restrict__ emask,
    const float* __restrict__ ts, const float* __restrict__ last_update,
    const float* __restrict__ memory, const float* __restrict__ time_w,
    const float* __restrict__ time_b, const int* __restrict__ ei,
    const void* __restrict__ timep)
{
    int b = blockIdx.x, tid = threadIdx.x;
    if (b < 2048) {
        int i = b * 2 + (tid >> 7);
        int h = tid & 127;
        float em = emask[i], sm = smask[i], dm = dmask[i];
        int   etv = et[i];
        float tsv = ts[i];
        float el  = last_update[eids[i]];
        float rel = tsv - el * dm;
        float isn = (etv == 3 || etv == 4) ? 1.f : 0.f;
        float targ = tsv * isn + rel * dm;
        float cosv = __cosf(targ * time_w[h] + time_b[h]) * em;
        int sid = sids[i], did = dids[i];
        float sv = memory[sid * H + h] * sm;
        float dv = memory[did * H + h] * dm;
        float ev = eemb[i * H + h];
        float typ = (float)etv;
        float* aS = g_aggS + sid * MSG;
        atomicAdd(aS + 0 * H + h, typ  * em);
        atomicAdd(aS + 1 * H + h, sv   * em);
        atomicAdd(aS + 2 * H + h, dv   * em);
        atomicAdd(aS + 3 * H + h, cosv * em);
        atomicAdd(aS + 4 * H + h, ev   * em);
        float* aD = g_aggD + did * MSG;
        atomicAdd(aD + 0 * H + h, typ  * dm);
        atomicAdd(aD + 1 * H + h, dv   * dm);
        atomicAdd(aD + 2 * H + h, sv   * dm);
        atomicAdd(aD + 3 * H + h, cosv * dm);
        atomicAdd(aD + 4 * H + h, ev   * dm);
        if (h == 0) { atomicAdd(&g_cntS[sid], 1.f); atomicAdd(&g_cntD[did], 1.f); }
    } else if (b < 4548) {
        int j = (b - 2048) * 256 + tid;
        if (j < NE) atomicAdd(&g_cnt[ei[NE + j]], 1);
    } else {
        int u = (b - 4548) * 256 + tid;
        if (u < g_ucount)
            g_urelt[u] = get_time(timep) - last_update[g_list[u]];
    }
}

// ------------------- K3: single-block scan of g_cnt -> g_off / g_cur -------------------
__global__ void __launch_bounds__(512) k_scan() {
    __shared__ int ssum[512];
    int t = threadIdx.x;
    const int CH = 40;
    int base = t * CH;
    int loc = 0;
#pragma unroll 4
    for (int i = 0; i < CH; i++) {
        int idx = base + i;
        if (idx < NN) loc += g_cnt[idx];
    }
    ssum[t] = loc;
    __syncthreads();
    for (int off = 1; off < 512; off <<= 1) {
        int v = (t >= off) ? ssum[t - off] : 0;
        __syncthreads();
        ssum[t] += v;
        __syncthreads();
    }
    int run = ssum[t] - loc;
    for (int i = 0; i < CH; i++) {
        int idx = base + i;
        if (idx < NN) {
            g_off[idx] = run;
            g_cur[idx] = run;
            run += g_cnt[idx];
        }
    }
    if (t == 511) g_off[NN] = ssum[511];
}

// ------------------- K4: both GRU GEMMs; z=0 gathers agg directly -------------------
__global__ void __launch_bounds__(256, 2) k_gru_gemms(
    const float* __restrict__ b_ih, const float* __restrict__ b_hh,
    const int* __restrict__ sids, const int* __restrict__ dids)
{
    int z = blockIdx.z;
    const float* WT   = z ? g_whhT : g_wihT;
    const float* bias = z ? b_hh   : b_ih;
    float*       C    = z ? g_GH   : g_GI;
    int K = z ? 128 : 640;
    const int N = 384;

    int row0 = blockIdx.x * 128;
    int col0 = blockIdx.y * 128;
    __shared__ unsigned sA[128 * 36];
    __shared__ unsigned sW[32 * 136];
    int tid = threadIdx.x, lane = tid & 31, wid = tid >> 5;
    int wm = wid & 3, wn = wid >> 2;
    int gid = lane >> 2, tig = lane & 3;

    const float* aptr[4];
    float ainv[4];
    if (z == 0) {
        bool isS = row0 < EVT;
#pragma unroll
        for (int l = 0; l < 4; l++) {
            int row = (tid + l * 256) >> 3;
            int r = row0 + row;
            int i = isS ? r : r - EVT;
            int id = isS ? sids[i] : dids[i];
            aptr[l] = (isS ? g_aggS : g_aggD) + (size_t)id * MSG;
            ainv[l] = 1.f / fmaxf((isS ? g_cntS : g_cntD)[id], 1.f);
        }
    }

    float acc[2][8][4];
#pragma unroll
    for (int mt = 0; mt < 2; mt++)
#pragma unroll
        for (int nt = 0; nt < 8; nt++)
#pragma unroll
            for (int c = 0; c < 4; c++) acc[mt][nt][c] = 0.f;

    for (int kc = 0; kc < K; kc += 32) {
#pragma unroll
        for (int l = 0; l < 4; l++) {
            int idx = tid + l * 256;
            int row = idx >> 3, c4 = (idx & 7) * 4;
            float4 v;
            if (z == 0) {
                v = *(const float4*)&aptr[l][kc + c4];
                v.x *= ainv[l]; v.y *= ainv[l]; v.z *= ainv[l]; v.w *= ainv[l];
            } else {
                v = *(const float4*)&g_Hst[(size_t)(row0 + row) * H + kc + c4];
            }
            uint4 t;
            t.x = f2tf32(v.x); t.y = f2tf32(v.y);
            t.z = f2tf32(v.z); t.w = f2tf32(v.w);
            *(uint4*)&sA[row * 36 + c4] = t;
        }
#pragma unroll
        for (int l = 0; l < 4; l++) {
            int idx = tid + l * 256;
            int k = idx >> 5, n4 = (idx & 31) * 4;
            float4 v = *(const float4*)&WT[(size_t)(kc + k) * N + col0 + n4];
            uint4 t;
            t.x = f2tf32(v.x); t.y = f2tf32(v.y);
            t.z = f2tf32(v.z); t.w = f2tf32(v.w);
            *(uint4*)&sW[k * 136 + n4] = t;
        }
        __syncthreads();
#pragma unroll
        for (int k8 = 0; k8 < 32; k8 += 8) {
            unsigned a[2][4];
#pragma unroll
            for (int mt = 0; mt < 2; mt++) {
                int r = wm * 32 + mt * 16;
                a[mt][0] = sA[(r + gid    ) * 36 + k8 + tig    ];
                a[mt][1] = sA[(r + gid + 8) * 36 + k8 + tig    ];
                a[mt][2] = sA[(r + gid    ) * 36 + k8 + tig + 4];
                a[mt][3] = sA[(r + gid + 8) * 36 + k8 + tig + 4];
            }
#pragma unroll
            for (int nt = 0; nt < 8; nt++) {
                int n = wn * 64 + nt * 8 + gid;
                unsigned b[2];
                b[0] = sW[(k8 + tig    ) * 136 + n];
                b[1] = sW[(k8 + tig + 4) * 136 + n];
                mma_tf32(acc[0][nt], a[0], b);
                mma_tf32(acc[1][nt], a[1], b);
            }
        }
        __syncthreads();
    }
#pragma unroll
    for (int mt = 0; mt < 2; mt++) {
#pragma unroll
        for (int nt = 0; nt < 8; nt++) {
            int col = col0 + wn * 64 + nt * 8 + tig * 2;
            float b0 = bias[col], b1 = bias[col + 1];
            int r0 = row0 + wm * 32 + mt * 16 + gid;
            float2 o0 = make_float2(acc[mt][nt][0] + b0, acc[mt][nt][1] + b1);
            float2 o1 = make_float2(acc[mt][nt][2] + b0, acc[mt][nt][3] + b1);
            *(float2*)&C[(size_t)r0 * N + col] = o0;
            *(float2*)&C[(size_t)(r0 + 8) * N + col] = o1;
        }
    }
}

// ------------------- K5: fused E-GEMM (A built on the fly: cos | EF gather) -------------------
__global__ void __launch_bounds__(256, 2) k_egemm(
    const float* __restrict__ EF, const float* __restrict__ tw,
    const float* __restrict__ tb, const float* __restrict__ WT,
    float* __restrict__ C)
{
    int M = g_ucount;
    int row0 = blockIdx.x * 128;
    if (row0 >= M) return;
    __shared__ unsigned sA[128 * 36];
    __shared__ unsigned sW[32 * 136];
    int tid = threadIdx.x, lane = tid & 31, wid = tid >> 5;
    int wm = wid & 3, wn = wid >> 2;
    int gid = lane >> 2, tig = lane & 3;

    float acc[2][8][4];
#pragma unroll
    for (int mt = 0; mt < 2; mt++)
#pragma unroll
        for (int nt = 0; nt < 8; nt++)
#pragma unroll
            for (int c = 0; c < 4; c++) acc[mt][nt][c] = 0.f;

    for (int kc = 0; kc < 256; kc += 32) {
#pragma unroll
        for (int l = 0; l < 4; l++) {
            int idx = tid + l * 256;
            int row = idx >> 3, c4 = (idx & 7) * 4;
            int r = row0 + row;
            float4 v = make_float4(0.f, 0.f, 0.f, 0.f);
            if (r < M) {
                int col = kc + c4;
                if (col < 128) {
                    float relt = g_urelt[r];
                    v.x = __cosf(relt * tw[col    ] + tb[col    ]);
                    v.y = __cosf(relt * tw[col + 1] + tb[col + 1]);
                    v.z = __cosf(relt * tw[col + 2] + tb[col + 2]);
                    v.w = __cosf(relt * tw[col + 3] + tb[col + 3]);
                } else {
                    int e = g_list[r];
                    v = *(const float4*)&EF[(size_t)e * H + col - 128];
                }
            }
            uint4 t;
            t.x = f2tf32(v.x); t.y = f2tf32(v.y);
            t.z = f2tf32(v.z); t.w = f2tf32(v.w);
            *(uint4*)&sA[row * 36 + c4] = t;
        }
#pragma unroll
        for (int l = 0; l < 4; l++) {
            int idx = tid + l * 256;
            int k = idx >> 5, n4 = (idx & 31) * 4;
            float4 v = *(const float4*)&WT[(size_t)(kc + k) * 128 + n4];
            uint4 t;
            t.x = f2tf32(v.x); t.y = f2tf32(v.y);
            t.z = f2tf32(v.z); t.w = f2tf32(v.w);
            *(uint4*)&sW[k * 136 + n4] = t;
        }
        __syncthreads();
#pragma unroll
        for (int k8 = 0; k8 < 32; k8 += 8) {
            unsigned a[2][4];
#pragma unroll
            for (int mt = 0; mt < 2; mt++) {
                int r = wm * 32 + mt * 16;
                a[mt][0] = sA[(r + gid    ) * 36 + k8 + tig    ];
                a[mt][1] = sA[(r + gid + 8) * 36 + k8 + tig    ];
                a[mt][2] = sA[(r + gid    ) * 36 + k8 + tig + 4];
                a[mt][3] = sA[(r + gid + 8) * 36 + k8 + tig + 4];
            }
#pragma unroll
            for (int nt = 0; nt < 8; nt++) {
                int n = wn * 64 + nt * 8 + gid;
                unsigned b[2];
                b[0] = sW[(k8 + tig    ) * 136 + n];
                b[1] = sW[(k8 + tig + 4) * 136 + n];
                mma_tf32(acc[0][nt], a[0], b);
                mma_tf32(acc[1][nt], a[1], b);
            }
        }
        __syncthreads();
    }
#pragma unroll
    for (int mt = 0; mt < 2; mt++) {
#pragma unroll
        for (int nt = 0; nt < 8; nt++) {
            int col = wn * 64 + nt * 8 + tig * 2;
            int r0 = row0 + wm * 32 + mt * 16 + gid;
            if (r0 < M) {
                float2 o = make_float2(acc[mt][nt][0], acc[mt][nt][1]);
                *(float2*)&C[(size_t)r0 * 128 + col] = o;
            }
            if (r0 + 8 < M) {
                float2 o = make_float2(acc[mt][nt][2], acc[mt][nt][3]);
                *(float2*)&C[(size_t)(r0 + 8) * 128 + col] = o;
            }
        }
    }
}

// ------------------- K6: gru_act + scatter + tag -------------------
__global__ void __launch_bounds__(256) k_phase4(
    const int* __restrict__ ei, const int* __restrict__ eids,
    const int* __restrict__ sids, const int* __restrict__ dids)
{
    int b = blockIdx.x, tid = threadIdx.x;
    if (b < 4096) {
        int idx = b * 256 + tid;
        int r = idx >> 7, h = idx & 127;
        float ir = g_GI[r * 384 + h];
        float iz = g_GI[r * 384 + 128 + h];
        float in_ = g_GI[r * 384 + 256 + h];
        float hr = g_GH[r * 384 + h];
        float hz = g_GH[r * 384 + 128 + h];
        float hn = g_GH[r * 384 + 256 + h];
        float rr = 1.f / (1.f + expf(-(ir + hr)));
        float zz = 1.f / (1.f + expf(-(iz + hz)));
        float nn = tanhf(in_ + rr * hn);
        g_newMem[idx] = (1.f - zz) * nn + zz * g_Hst[idx];
    } else if (b < 5346) {
        int j = (b - 4096) * 256 + tid;
        if (j < NE) {
            int d = ei[NE + j];
            int pos = atomicAdd(&g_cur[d], 1);
            g_ss[pos] = ei[j];
            g_su[pos] = g_slot[eids[j]];
        }
    } else {
        int t = (b - 5346) * 256 + tid;
        if (t < 2 * EVT) {
            bool isD = t >= EVT;
            int i = isD ? t - EVT : t;
            int id = isD ? dids[i] : sids[i];
            int key = (isD ? DSTBIT : 0) | (i + 1);
            atomicMax(&g_tag[id], key);
        }
    }
}

// ------------------- K7: q|k|v|skip GEMM with fused x gather -------------------
__global__ void __launch_bounds__(256, 2) k_qkvs_gemm(
    const int* __restrict__ node_ids, const float* __restrict__ NF,
    const float* __restrict__ memory)
{
    const int M = NN, K = 128, N = 512;
    int row0 = blockIdx.x * 128;
    int col0 = blockIdx.y * 128;
    __shared__ unsigned sA[128 * 36];
    __shared__ unsigned sW[32 * 136];
    int tid = threadIdx.x, lane = tid & 31, wid = tid >> 5;
    int wm = wid & 3, wn = wid >> 2;
    int gid = lane >> 2, tig = lane & 3;

    float acc[2][8][4];
#pragma unroll
    for (int mt = 0; mt < 2; mt++)
#pragma unroll
        for (int nt = 0; nt < 8; nt++)
#pragma unroll
            for (int c = 0; c < 4; c++) acc[mt][nt][c] = 0.f;

    for (int kc = 0; kc < K; kc += 32) {
#pragma unroll
        for (int l = 0; l < 4; l++) {
            int idx = tid + l * 256;
            int row = idx >> 3, c4 = (idx & 7) * 4;
            int r = row0 + row;
            float4 v = make_float4(0.f, 0.f, 0.f, 0.f);
            if (r < M) {
                int nid = node_ids[r];
                int tg = g_tag[nid];
                const float* mp;
                if (tg == 0)          mp = &memory[(size_t)nid * H];
                else if (tg & DSTBIT) mp = &g_newMem[(size_t)(EVT + (tg & ~DSTBIT) - 1) * H];
                else                  mp = &g_newMem[(size_t)(tg - 1) * H];
                float4 nf = *(const float4*)&NF[(size_t)nid * H + kc + c4];
                float4 mv = *(const float4*)&mp[kc + c4];
                v = make_float4(nf.x + mv.x, nf.y + mv.y, nf.z + mv.z, nf.w + mv.w);
            }
            uint4 t;
            t.x = f2tf32(v.x); t.y = f2tf32(v.y);
            t.z = f2tf32(v.z); t.w = f2tf32(v.w);
            *(uint4*)&sA[row * 36 + c4] = t;
        }
#pragma unroll
        for (int l = 0; l < 4; l++) {
            int idx = tid + l * 256;
            int k = idx >> 5, n4 = (idx & 31) * 4;
            float4 v = *(const float4*)&g_wcT[(size_t)(kc + k) * N + col0 + n4];
            uint4 t;
            t.x = f2tf32(v.x); t.y = f2tf32(v.y);
            t.z = f2tf32(v.z); t.w = f2tf32(v.w);
            *(uint4*)&sW[k * 136 + n4] = t;
        }
        __syncthreads();
#pragma unroll
        for (int k8 = 0; k8 < 32; k8 += 8) {
            unsigned a[2][4];
#pragma unroll
            for (int mt = 0; mt < 2; mt++) {
                int r = wm * 32 + mt * 16;
                a[mt][0] = sA[(r + gid    ) * 36 + k8 + tig    ];
                a[mt][1] = sA[(r + gid + 8) * 36 + k8 + tig    ];
                a[mt][2] = sA[(r + gid    ) * 36 + k8 + tig + 4];
                a[mt][3] = sA[(r + gid + 8) * 36 + k8 + tig + 4];
            }
#pragma unroll
            for (int nt = 0; nt < 8; nt++) {
                int n = wn * 64 + nt * 8 + gid;
                unsigned b[2];
                b[0] = sW[(k8 + tig    ) * 136 + n];
                b[1] = sW[(k8 + tig + 4) * 136 + n];
                mma_tf32(acc[0][nt], a[0], b);
                mma_tf32(acc[1][nt], a[1], b);
            }
        }
        __syncthreads();
    }
#pragma unroll
    for (int mt = 0; mt < 2; mt++) {
#pragma unroll
        for (int nt = 0; nt < 8; nt++) {
            int col = col0 + wn * 64 + nt * 8 + tig * 2;
            float b0 = g_bc[col], b1 = g_bc[col + 1];
            int r0 = row0 + wm * 32 + mt * 16 + gid;
            if (r0 < M) {
                float2 o = make_float2(acc[mt][nt][0] + b0, acc[mt][nt][1] + b1);
                *(float2*)&g_qkvs[(size_t)r0 * N + col] = o;
            }
            if (r0 + 8 < M) {
                float2 o = make_float2(acc[mt][nt][2] + b0, acc[mt][nt][3] + b1);
                *(float2*)&g_qkvs[(size_t)(r0 + 8) * N + col] = o;
            }
        }
    }
}

// ------------------- K8: attention (full-warp, 2 independent softmax states) + unflag -------------------
__global__ void __launch_bounds__(256) k_attn(float* __restrict__ out,
                                              const int* __restrict__ eids) {
    int b = blockIdx.x;
    if (b >= 2500) {
        int j = (b - 2500) * 256 + threadIdx.x;
        if (j < NE) g_flag[eids[j]] = 0;
        if (j == 0) g_ucount = 0;
        return;
    }
    int warp = threadIdx.x >> 5, lane = threadIdx.x & 31;
    int d = b * 8 + warp;
    if (d >= NN) return;
    int off0 = g_off[d], off1 = g_off[d + 1];

    float4 q4 = *(const float4*)&g_qkvs[(size_t)d * 512 + lane * 4];
    // two independent online-softmax states (even / odd edges)
    float mA = -1e30f, denA = 0.f;
    float4 accA = make_float4(0.f, 0.f, 0.f, 0.f);
    float mB = -1e30f, denB = 0.f;
    float4 accB = make_float4(0.f, 0.f, 0.f, 0.f);

    for (int i = off0; i < off1; i += 2) {
        bool has2 = (i + 1 < off1);               // warp-uniform
        int s0 = g_ss[i], u0 = g_su[i];
        float4 k0 = *(const float4*)&g_qkvs[(size_t)s0 * 512 + 128 + lane * 4];
        float4 e0 = *(const float4*)&g_Ec  [(size_t)u0 * H   +       lane * 4];
        float4 v0 = *(const float4*)&g_qkvs[(size_t)s0 * 512 + 256 + lane * 4];
        float p0 = q4.x * (k0.x + e0.x) + q4.y * (k0.y + e0.y)
                 + q4.z * (k0.z + e0.z) + q4.w * (k0.w + e0.w);
        float4 k1, e1, v1;
        float p1 = 0.f;
        if (has2) {
            int s1 = g_ss[i + 1], u1 = g_su[i + 1];
            k1 = *(const float4*)&g_qkvs[(size_t)s1 * 512 + 128 + lane * 4];
            e1 = *(const float4*)&g_Ec  [(size_t)u1 * H   +       lane * 4];
            v1 = *(const float4*)&g_qkvs[(size_t)s1 * 512 + 256 + lane * 4];
            p1 = q4.x * (k1.x + e1.x) + q4.y * (k1.y + e1.y)
               + q4.z * (k1.z + e1.z) + q4.w * (k1.w + e1.w);
        }
#pragma unroll
        for (int o = 16; o; o >>= 1) {
            p0 += __shfl_xor_sync(0xffffffffu, p0, o);
            p1 += __shfl_xor_sync(0xffffffffu, p1, o);
        }
        // state A <- edge i
        {
            float a = p0 * 0.08838834764831845f;
            float mn = fmaxf(mA, a);
            float scale = __expf(mA - mn);
            float w = __expf(a - mn);
            denA = denA * scale + w;
            accA.x = accA.x * scale + w * (v0.x + e0.x);
            accA.y = accA.y * scale + w * (v0.y + e0.y);
            accA.z = accA.z * scale + w * (v0.z + e0.z);
            accA.w = accA.w * scale + w * (v0.w + e0.w);
            mA = mn;
        }
        // state B <- edge i+1
        if (has2) {
            float a = p1 * 0.08838834764831845f;
            float mn = fmaxf(mB, a);
            float scale = __expf(mB - mn);
            float w = __expf(a - mn);
            denB = denB * scale + w;
            accB.x = accB.x * scale + w * (v1.x + e1.x);
            accB.y = accB.y * scale + w * (v1.y + e1.y);
            accB.z = accB.z * scale + w * (v1.z + e1.z);
            accB.w = accB.w * scale + w * (v1.w + e1.w);
            mB = mn;
        }
    }
    // merge B into A
    {
        float mn = fmaxf(mA, mB);
        float sA = __expf(mA - mn), sB = __expf(mB - mn);
        denA = denA * sA + denB * sB;
        accA.x = accA.x * sA + accB.x * sB;
        accA.y = accA.y * sA + accB.y * sB;
        accA.z = accA.z * sA + accB.z * sB;
        accA.w = accA.w * sA + accB.w * sB;
    }
    float rden = 1.f / fmaxf(denA, 1e-16f);
    float4 sk = *(const float4*)&g_qkvs[(size_t)d * 512 + 384 + lane * 4];
    float4 o4 = make_float4(sk.x + accA.x * rden, sk.y + accA.y * rden,
                            sk.z + accA.z * rden, sk.w + accA.w * rden);
    *(float4*)&out[(size_t)d * H + lane * 4] = o4;
}

// ------------------- host -------------------
static float* symf(const void* s) {
    void* p = nullptr;
    cudaGetSymbolAddress(&p, s);
    return (float*)p;
}

extern "C" void kernel_launch(void* const* d_in, const int* in_sizes, int n_in,
                              void* d_out, int out_size)
{
    const int*   event_type_ids = (const int*)  d_in[0];
    const int*   src_ids        = (const int*)  d_in[1];
    const float* src_mask       = (const float*)d_in[2];
    const int*   dst_ids        = (const int*)  d_in[3];
    const float* dst_mask       = (const float*)d_in[4];
    const int*   event_edge_ids = (const int*)  d_in[5];
    const float* event_emb      = (const float*)d_in[6];
    const float* event_mask     = (const float*)d_in[7];
    const float* event_ts       = (const float*)d_in[8];
    const int*   node_ids       = (const int*)  d_in[9];
    const int*   edge_ids       = (const int*)  d_in[10];
    const int*   edge_index     = (const int*)  d_in[11];
    const void*  timep          =               d_in[12];
    const float* memory         = (const float*)d_in[13];
    const float* last_update    = (const float*)d_in[14];
    const float* node_features  = (const float*)d_in[15];
    const float* edge_features  = (const float*)d_in[16];
    const float* time_w         = (const float*)d_in[17];
    const float* time_b         = (const float*)d_in[18];
    const float* gru_w_ih       = (const float*)d_in[19];
    const float* gru_w_hh       = (const float*)d_in[20];
    const float* gru_b_ih       = (const float*)d_in[21];
    const float* gru_b_hh       = (const float*)d_in[22];
    const float* wq             = (const float*)d_in[23];
    const float* bq             = (const float*)d_in[24];
    const float* wk             = (const float*)d_in[25];
    const float* bk             = (const float*)d_in[26];
    const float* wv             = (const float*)d_in[27];
    const float* bv             = (const float*)d_in[28];
    const float* we             = (const float*)d_in[29];
    const float* wskip          = (const float*)d_in[30];
    const float* bskip          = (const float*)d_in[31];
    float* out = (float*)d_out;

    float* pEc  = symf(g_Ec);
    float* pweT = symf(g_weT);

    // K1: prep (transposes, packw, flag, cnt0, zero, Hst build)
    k_prep<<<11057, 256>>>(gru_w_ih, gru_w_hh, we, wq, wk, wv, wskip,
                           bq, bk, bv, bskip, edge_ids, src_ids, dst_ids, memory);
    // K2: msg + hist + urelt
    k_phase2<<<6892, 256>>>(event_type_ids, src_ids, src_mask, dst_ids, dst_mask,
                            event_edge_ids, event_emb, event_mask, event_ts,
                            last_update, memory, time_w, time_b, edge_index, timep);
    // K3: scan
    k_scan<<<1, 512>>>();
    // K4: GRU GEMMs (z=0 gathers agg directly)
    k_gru_gemms<<<dim3(64, 3, 2), 256>>>(gru_b_ih, gru_b_hh, src_ids, dst_ids);
    // K5: fused E-GEMM over unique eids
    k_egemm<<<(MAXE + 127) / 128, 256>>>(edge_features, time_w, time_b, pweT, pEc);
    // K6: gru_act + scatter + tag
    k_phase4<<<5378, 256>>>(edge_index, edge_ids, src_ids, dst_ids);
    // K7: q|k|v|skip GEMM with fused x gather
    k_qkvs_gemm<<<dim3((NN + 127) / 128, 4), 256>>>(node_ids, node_features, memory);
    // K8: attention (2-state ILP) + unflag
    k_attn<<<2500 + (NE + 255) / 256, 256>>>(out, edge_ids);
}

// round 16
// speedup vs baseline: 1.0989x; 1.0989x over previous
#include <cuda_runtime.h>
#include <math.h>

#define H      128
#define EVT    4096
#define NN     20000
#define NE     320000
#define MAXN   100000
#define MAXE   300000
#define MSG    640
#define DSTBIT (1 << 30)

// block-range layout for k_mid
#define GRU_BLKS   384                    // 64 x 3 x 2
#define EG_BLKS    ((MAXE + 127) / 128)   // 2344/... = 2344? (300000/128 = 2344)
#define SC_BLKS    ((NE + 255) / 256)     // 1250
#define TAG_BLKS   32
#define MID_B1     GRU_BLKS
#define MID_B2     (MID_B1 + EG_BLKS)
#define MID_B3     (MID_B2 + SC_BLKS)
#define MID_TOT    (MID_B3 + TAG_BLKS)

// ------------------- device scratch (static, allowed) -------------------
__device__ float    g_aggS[MAXN * MSG];
__device__ float    g_aggD[MAXN * MSG];
__device__ float    g_cntS[MAXN];
__device__ float    g_cntD[MAXN];
__device__ float    g_Hst [2 * EVT * H];
__device__ float    g_GI  [2 * EVT * 384];
__device__ float    g_GH  [2 * EVT * 384];
__device__ float    g_newMem[2 * EVT * H];
__device__ int      g_tag [MAXN];        // 0-init; monotone atomicMax keys
// unique-edge machinery
__device__ int      g_flag[MAXE];        // 0-init; cleared at end of each launch
__device__ int      g_list[MAXE];
__device__ int      g_slot[MAXE];
__device__ int      g_ucount;            // 0-init; reset at end of each launch
__device__ float    g_urelt[MAXE];
__device__ float    g_Ec  [MAXE * H];
__device__ float    g_qkvs[NN * 512];    // [q | k | v | skip]
// dst-sorted edge machinery
__device__ int      g_cnt [NN];
__device__ int      g_off [NN + 1];
__device__ int      g_cur [NN];
__device__ int      g_ss  [NE];          // src, sorted by dst
__device__ int      g_su  [NE];          // unique-eid slot, sorted by dst
// weights
__device__ float    g_wihT[640 * 384];
__device__ float    g_whhT[128 * 384];
__device__ float    g_weT [256 * 128];
__device__ float    g_wcT [128 * 512];
__device__ float    g_bc  [512];

// ------------------- helpers -------------------
__device__ __forceinline__ float get_time(const void* p) {
    int iv = *(const int*)p;
    if (iv > -1000000 && iv < 1000000) return (float)iv;
    return *(const float*)p;
}
__device__ __forceinline__ unsigned f2tf32(float f) {
    unsigned r;
    asm("cvt.rna.tf32.f32 %0, %1;" : "=r"(r) : "f"(f));
    return r;
}
__device__ __forceinline__ void mma_tf32(float* d, const unsigned* a, const unsigned* b) {
    asm("mma.sync.aligned.m16n8k8.row.col.f32.tf32.tf32.f32 "
        "{%0,%1,%2,%3}, {%4,%5,%6,%7}, {%8,%9}, {%0,%1,%2,%3};"
        : "+f"(d[0]), "+f"(d[1]), "+f"(d[2]), "+f"(d[3])
        : "r"(a[0]), "r"(a[1]), "r"(a[2]), "r"(a[3]), "r"(b[0]), "r"(b[1]));
}

// ------------------- K1: fused prep (all independent) -------------------
// [0,960) wihT | [960,1152) whhT | [1152,1280) weT | [1280,1536) packw
// [1536,2786) flag | [2786,2865) cnt0 | [2865,6961) zero | [6961,11057) Hst
__global__ void __launch_bounds__(256) k_prep(
    const float* __restrict__ gru_w_ih, const float* __restrict__ gru_w_hh,
    const float* __restrict__ we,
    const float* __restrict__ wq, const float* __restrict__ wk,
    const float* __restrict__ wv, const float* __restrict__ ws,
    const float* __restrict__ bq, const float* __restrict__ bk,
    const float* __restrict__ bv, const float* __restrict__ bs,
    const int* __restrict__ eids,
    const int* __restrict__ sids, const int* __restrict__ dids,
    const float* __restrict__ memory)
{
    int b = blockIdx.x, tid = threadIdx.x;
    if (b < 960) {
        int o = b * 256 + tid;
        int k = o / 384, n = o % 384;
        g_wihT[o] = gru_w_ih[n * 640 + k];
    } else if (b < 1152) {
        int o = (b - 960) * 256 + tid;
        int k = o / 384, n = o % 384;
        g_whhT[o] = gru_w_hh[n * 128 + k];
    } else if (b < 1280) {
        int o = (b - 1152) * 256 + tid;
        int k = o / 128, n = o % 128;
        g_weT[o] = we[n * 256 + k];
    } else if (b < 1536) {
        int o = (b - 1280) * 256 + tid;
        int k = o >> 9, n = o & 511;
        int grp = n >> 7, r = n & 127;
        const float* w = (grp == 0) ? wq : (grp == 1) ? wk : (grp == 2) ? wv : ws;
        g_wcT[o] = w[r * 128 + k];
        if (k == 0) {
            const float* bb = (grp == 0) ? bq : (grp == 1) ? bk : (grp == 2) ? bv : bs;
            g_bc[n] = bb[r];
        }
    } else if (b < 2786) {
        int j = (b - 1536) * 256 + tid;
        if (j < NE) {
            int e = eids[j];
            if (atomicExch(&g_flag[e], 1) == 0) {
                int u = atomicAdd(&g_ucount, 1);
                g_list[u] = e;
                g_slot[e] = u;
            }
        }
    } else if (b < 2865) {
        int i = (b - 2786) * 256 + tid;
        if (i < NN) g_cnt[i] = 0;
    } else if (b < 6961) {
        int i = b - 2865;
        int sid = sids[i], did = dids[i];
        for (int t = tid; t < MSG; t += 256) {
            g_aggS[sid * MSG + t] = 0.f;
            g_aggD[did * MSG + t] = 0.f;
        }
        if (tid == 0) { g_cntS[sid] = 0.f; g_cntD[did] = 0.f; }
    } else {
        int rr = (b - 6961) * 2 + (tid >> 7);   // row in [0, 2*EVT)
        int h = tid & 127;
        bool isS = rr < EVT;
        int i = isS ? rr : rr - EVT;
        int id = isS ? sids[i] : dids[i];
        g_Hst[rr * H + h] = memory[id * H + h];
    }
}

// ------------------- K2: msg + hist + urelt -------------------
__global__ void __launch_bounds__(256) k_phase2(
    const int* __restrict__ et, const int* __restrict__ sids,
    const float* __restrict__ smask, const int* __restrict__ dids,
    const float* __restrict__ dmask, const int* __restrict__ eids,
    const float* __restrict__ eemb, const float* __restrict__ emask,
    const float* __restrict__ ts, const float* __restrict__ last_update,
    const float* __restrict__ memory, const float* __restrict__ time_w,
    const float* __restrict__ time_b, const int* __restrict__ ei,
    const void* __restrict__ timep)
{
    int b = blockIdx.x, tid = threadIdx.x;
    if (b < 2048) {
        int i = b * 2 + (tid >> 7);
        int h = tid & 127;
        float em = emask[i], sm = smask[i], dm = dmask[i];
        int   etv = et[i];
        float tsv = ts[i];
        float el  = last_update[eids[i]];
        float rel = tsv - el * dm;
        float isn = (etv == 3 || etv == 4) ? 1.f : 0.f;
        float targ = tsv * isn + rel * dm;
        float cosv = __cosf(targ * time_w[h] + time_b[h]) * em;
        int sid = sids[i], did = dids[i];
        float sv = memory[sid * H + h] * sm;
        float dv = memory[did * H + h] * dm;
        float ev = eemb[i * H + h];
        float typ = (float)etv;
        float* aS = g_aggS + sid * MSG;
        atomicAdd(aS + 0 * H + h, typ  * em);
        atomicAdd(aS + 1 * H + h, sv   * em);
        atomicAdd(aS + 2 * H + h, dv   * em);
        atomicAdd(aS + 3 * H + h, cosv * em);
        atomicAdd(aS + 4 * H + h, ev   * em);
        float* aD = g_aggD + did * MSG;
        atomicAdd(aD + 0 * H + h, typ  * dm);
        atomicAdd(aD + 1 * H + h, dv   * dm);
        atomicAdd(aD + 2 * H + h, sv   * dm);
        atomicAdd(aD + 3 * H + h, cosv * dm);
        atomicAdd(aD + 4 * H + h, ev   * dm);
        if (h == 0) { atomicAdd(&g_cntS[sid], 1.f); atomicAdd(&g_cntD[did], 1.f); }
    } else if (b < 4548) {
        int j = (b - 2048) * 256 + tid;
        if (j < NE) atomicAdd(&g_cnt[ei[NE + j]], 1);
    } else {
        int u = (b - 4548) * 256 + tid;
        if (u < g_ucount)
            g_urelt[u] = get_time(timep) - last_update[g_list[u]];
    }
}

// ------------------- K3: single-block scan of g_cnt -> g_off / g_cur -------------------
__global__ void __launch_bounds__(512) k_scan() {
    __shared__ int ssum[512];
    int t = threadIdx.x;
    const int CH = 40;
    int base = t * CH;
    int loc = 0;
#pragma unroll 4
    for (int i = 0; i < CH; i++) {
        int idx = base + i;
        if (idx < NN) loc += g_cnt[idx];
    }
    ssum[t] = loc;
    __syncthreads();
    for (int off = 1; off < 512; off <<= 1) {
        int v = (t >= off) ? ssum[t - off] : 0;
        __syncthreads();
        ssum[t] += v;
        __syncthreads();
    }
    int run = ssum[t] - loc;
    for (int i = 0; i < CH; i++) {
        int idx = base + i;
        if (idx < NN) {
            g_off[idx] = run;
            g_cur[idx] = run;
            run += g_cnt[idx];
        }
    }
    if (t == 511) g_off[NN] = ssum[511];
}

// ------------------- K4: merged mid phase -------------------
// [0, 384)           : GRU GEMMs (b -> bx=b%64, by=(b/64)%3, bz=b/192)
// [384, 384+EG)      : E-GEMM over unique eids
// [.., +SC)          : scatter (needs g_cur from scan, g_slot from prep)
// [.., +32)          : tag
__global__ void __launch_bounds__(256, 2) k_mid(
    const float* __restrict__ b_ih, const float* __restrict__ b_hh,
    const int* __restrict__ sids, const int* __restrict__ dids,
    const float* __restrict__ EF, const float* __restrict__ tw,
    const float* __restrict__ tb,
    const int* __restrict__ ei, const int* __restrict__ eids)
{
    __shared__ unsigned sA[128 * 36];
    __shared__ unsigned sW[32 * 136];
    int b = blockIdx.x, tid = threadIdx.x;

    if (b >= MID_B2) {
        if (b < MID_B3) {                 // scatter
            int j = (b - MID_B2) * 256 + tid;
            if (j < NE) {
                int d = ei[NE + j];
                int pos = atomicAdd(&g_cur[d], 1);
                g_ss[pos] = ei[j];
                g_su[pos] = g_slot[eids[j]];
            }
        } else {                          // tag
            int t = (b - MID_B3) * 256 + tid;
            if (t < 2 * EVT) {
                bool isD = t >= EVT;
                int i = isD ? t - EVT : t;
                int id = isD ? dids[i] : sids[i];
                int key = (isD ? DSTBIT : 0) | (i + 1);
                atomicMax(&g_tag[id], key);
            }
        }
        return;
    }

    int lane = tid & 31, wid = tid >> 5;
    int wm = wid & 3, wn = wid >> 2;
    int gid = lane >> 2, tig = lane & 3;

    float acc[2][8][4];
#pragma unroll
    for (int mt = 0; mt < 2; mt++)
#pragma unroll
        for (int nt = 0; nt < 8; nt++)
#pragma unroll
            for (int c = 0; c < 4; c++) acc[mt][nt][c] = 0.f;

    if (b < MID_B1) {
        // ---------------- GRU GEMMs ----------------
        int bx = b & 63, by = (b >> 6) % 3, bz = b / 192;
        const float* WT   = bz ? g_whhT : g_wihT;
        const float* bias = bz ? b_hh   : b_ih;
        float*       C    = bz ? g_GH   : g_GI;
        int K = bz ? 128 : 640;
        const int N = 384;
        int row0 = bx * 128;
        int col0 = by * 128;

        const float* aptr[4];
        float ainv[4];
        if (bz == 0) {
            bool isS = row0 < EVT;
#pragma unroll
            for (int l = 0; l < 4; l++) {
                int row = (tid + l * 256) >> 3;
                int r = row0 + row;
                int i = isS ? r : r - EVT;
                int id = isS ? sids[i] : dids[i];
                aptr[l] = (isS ? g_aggS : g_aggD) + (size_t)id * MSG;
                ainv[l] = 1.f / fmaxf((isS ? g_cntS : g_cntD)[id], 1.f);
            }
        }

        for (int kc = 0; kc < K; kc += 32) {
#pragma unroll
            for (int l = 0; l < 4; l++) {
                int idx = tid + l * 256;
                int row = idx >> 3, c4 = (idx & 7) * 4;
                float4 v;
                if (bz == 0) {
                    v = *(const float4*)&aptr[l][kc + c4];
                    v.x *= ainv[l]; v.y *= ainv[l]; v.z *= ainv[l]; v.w *= ainv[l];
                } else {
                    v = *(const float4*)&g_Hst[(size_t)(row0 + row) * H + kc + c4];
                }
                uint4 t;
                t.x = f2tf32(v.x); t.y = f2tf32(v.y);
                t.z = f2tf32(v.z); t.w = f2tf32(v.w);
                *(uint4*)&sA[row * 36 + c4] = t;
            }
#pragma unroll
            for (int l = 0; l < 4; l++) {
                int idx = tid + l * 256;
                int k = idx >> 5, n4 = (idx & 31) * 4;
                float4 v = *(const float4*)&WT[(size_t)(kc + k) * N + col0 + n4];
                uint4 t;
                t.x = f2tf32(v.x); t.y = f2tf32(v.y);
                t.z = f2tf32(v.z); t.w = f2tf32(v.w);
                *(uint4*)&sW[k * 136 + n4] = t;
            }
            __syncthreads();
#pragma unroll
            for (int k8 = 0; k8 < 32; k8 += 8) {
                unsigned a[2][4];
#pragma unroll
                for (int mt = 0; mt < 2; mt++) {
                    int r = wm * 32 + mt * 16;
                    a[mt][0] = sA[(r + gid    ) * 36 + k8 + tig    ];
                    a[mt][1] = sA[(r + gid + 8) * 36 + k8 + tig    ];
                    a[mt][2] = sA[(r + gid    ) * 36 + k8 + tig + 4];
                    a[mt][3] = sA[(r + gid + 8) * 36 + k8 + tig + 4];
                }
#pragma unroll
                for (int nt = 0; nt < 8; nt++) {
                    int n = wn * 64 + nt * 8 + gid;
                    unsigned bb[2];
                    bb[0] = sW[(k8 + tig    ) * 136 + n];
                    bb[1] = sW[(k8 + tig + 4) * 136 + n];
                    mma_tf32(acc[0][nt], a[0], bb);
                    mma_tf32(acc[1][nt], a[1], bb);
                }
            }
            __syncthreads();
        }
#pragma unroll
        for (int mt = 0; mt < 2; mt++) {
#pragma unroll
            for (int nt = 0; nt < 8; nt++) {
                int col = col0 + wn * 64 + nt * 8 + tig * 2;
                float b0 = bias[col], b1 = bias[col + 1];
                int r0 = row0 + wm * 32 + mt * 16 + gid;
                float2 o0 = make_float2(acc[mt][nt][0] + b0, acc[mt][nt][1] + b1);
                float2 o1 = make_float2(acc[mt][nt][2] + b0, acc[mt][nt][3] + b1);
                *(float2*)&C[(size_t)r0 * 384 + col] = o0;
                *(float2*)&C[(size_t)(r0 + 8) * 384 + col] = o1;
            }
        }
    } else {
        // ---------------- E-GEMM ----------------
        int M = g_ucount;
        int row0 = (b - MID_B1) * 128;
        if (row0 >= M) return;

        for (int kc = 0; kc < 256; kc += 32) {
#pragma unroll
            for (int l = 0; l < 4; l++) {
                int idx = tid + l * 256;
                int row = idx >> 3, c4 = (idx & 7) * 4;
                int r = row0 + row;
                float4 v = make_float4(0.f, 0.f, 0.f, 0.f);
                if (r < M) {
                    int col = kc + c4;
                    if (col < 128) {
                        float relt = g_urelt[r];
                        v.x = __cosf(relt * tw[col    ] + tb[col    ]);
                        v.y = __cosf(relt * tw[col + 1] + tb[col + 1]);
                        v.z = __cosf(relt * tw[col + 2] + tb[col + 2]);
                        v.w = __cosf(relt * tw[col + 3] + tb[col + 3]);
                    } else {
                        int e = g_list[r];
                        v = *(const float4*)&EF[(size_t)e * H + col - 128];
                    }
                }
                uint4 t;
                t.x = f2tf32(v.x); t.y = f2tf32(v.y);
                t.z = f2tf32(v.z); t.w = f2tf32(v.w);
                *(uint4*)&sA[row * 36 + c4] = t;
            }
#pragma unroll
            for (int l = 0; l < 4; l++) {
                int idx = tid + l * 256;
                int k = idx >> 5, n4 = (idx & 31) * 4;
                float4 v = *(const float4*)&g_weT[(size_t)(kc + k) * 128 + n4];
                uint4 t;
                t.x = f2tf32(v.x); t.y = f2tf32(v.y);
                t.z = f2tf32(v.z); t.w = f2tf32(v.w);
                *(uint4*)&sW[k * 136 + n4] = t;
            }
            __syncthreads();
#pragma unroll
            for (int k8 = 0; k8 < 32; k8 += 8) {
                unsigned a[2][4];
#pragma unroll
                for (int mt = 0; mt < 2; mt++) {
                    int r = wm * 32 + mt * 16;
                    a[mt][0] = sA[(r + gid    ) * 36 + k8 + tig    ];
                    a[mt][1] = sA[(r + gid + 8) * 36 + k8 + tig    ];
                    a[mt][2] = sA[(r + gid    ) * 36 + k8 + tig + 4];
                    a[mt][3] = sA[(r + gid + 8) * 36 + k8 + tig + 4];
                }
#pragma unroll
                for (int nt = 0; nt < 8; nt++) {
                    int n = wn * 64 + nt * 8 + gid;
                    unsigned bb[2];
                    bb[0] = sW[(k8 + tig    ) * 136 + n];
                    bb[1] = sW[(k8 + tig + 4) * 136 + n];
                    mma_tf32(acc[0][nt], a[0], bb);
                    mma_tf32(acc[1][nt], a[1], bb);
                }
            }
            __syncthreads();
        }
#pragma unroll
        for (int mt = 0; mt < 2; mt++) {
#pragma unroll
            for (int nt = 0; nt < 8; nt++) {
                int col = wn * 64 + nt * 8 + tig * 2;
                int r0 = row0 + wm * 32 + mt * 16 + gid;
                if (r0 < M) {
                    float2 o = make_float2(acc[mt][nt][0], acc[mt][nt][1]);
                    *(float2*)&g_Ec[(size_t)r0 * 128 + col] = o;
                }
                if (r0 + 8 < M) {
                    float2 o = make_float2(acc[mt][nt][2], acc[mt][nt][3]);
                    *(float2*)&g_Ec[(size_t)(r0 + 8) * 128 + col] = o;
                }
            }
        }
    }
}

// ------------------- K5: gru_act only -------------------
__global__ void __launch_bounds__(256) k_act() {
    int idx = blockIdx.x * 256 + threadIdx.x;
    int r = idx >> 7, h = idx & 127;
    float ir = g_GI[r * 384 + h];
    float iz = g_GI[r * 384 + 128 + h];
    float in_ = g_GI[r * 384 + 256 + h];
    float hr = g_GH[r * 384 + h];
    float hz = g_GH[r * 384 + 128 + h];
    float hn = g_GH[r * 384 + 256 + h];
    float rr = 1.f / (1.f + expf(-(ir + hr)));
    float zz = 1.f / (1.f + expf(-(iz + hz)));
    float nn = tanhf(in_ + rr * hn);
    g_newMem[idx] = (1.f - zz) * nn + zz * g_Hst[idx];
}

// ------------------- K6: q|k|v|skip GEMM with fused x gather -------------------
__global__ void __launch_bounds__(256, 2) k_qkvs_gemm(
    const int* __restrict__ node_ids, const float* __restrict__ NF,
    const float* __restrict__ memory)
{
    const int M = NN, K = 128, N = 512;
    int row0 = blockIdx.x * 128;
    int col0 = blockIdx.y * 128;
    __shared__ unsigned sA[128 * 36];
    __shared__ unsigned sW[32 * 136];
    int tid = threadIdx.x, lane = tid & 31, wid = tid >> 5;
    int wm = wid & 3, wn = wid >> 2;
    int gid = lane >> 2, tig = lane & 3;

    float acc[2][8][4];
#pragma unroll
    for (int mt = 0; mt < 2; mt++)
#pragma unroll
        for (int nt = 0; nt < 8; nt++)
#pragma unroll
            for (int c = 0; c < 4; c++) acc[mt][nt][c] = 0.f;

    for (int kc = 0; kc < K; kc += 32) {
#pragma unroll
        for (int l = 0; l < 4; l++) {
            int idx = tid + l * 256;
            int row = idx >> 3, c4 = (idx & 7) * 4;
            int r = row0 + row;
            float4 v = make_float4(0.f, 0.f, 0.f, 0.f);
            if (r < M) {
                int nid = node_ids[r];
                int tg = g_tag[nid];
                const float* mp;
                if (tg == 0)          mp = &memory[(size_t)nid * H];
                else if (tg & DSTBIT) mp = &g_newMem[(size_t)(EVT + (tg & ~DSTBIT) - 1) * H];
                else                  mp = &g_newMem[(size_t)(tg - 1) * H];
                float4 nf = *(const float4*)&NF[(size_t)nid * H + kc + c4];
                float4 mv = *(const float4*)&mp[kc + c4];
                v = make_float4(nf.x + mv.x, nf.y + mv.y, nf.z + mv.z, nf.w + mv.w);
            }
            uint4 t;
            t.x = f2tf32(v.x); t.y = f2tf32(v.y);
            t.z = f2tf32(v.z); t.w = f2tf32(v.w);
            *(uint4*)&sA[row * 36 + c4] = t;
        }
#pragma unroll
        for (int l = 0; l < 4; l++) {
            int idx = tid + l * 256;
            int k = idx >> 5, n4 = (idx & 31) * 4;
            float4 v = *(const float4*)&g_wcT[(size_t)(kc + k) * N + col0 + n4];
            uint4 t;
            t.x = f2tf32(v.x); t.y = f2tf32(v.y);
            t.z = f2tf32(v.z); t.w = f2tf32(v.w);
            *(uint4*)&sW[k * 136 + n4] = t;
        }
        __syncthreads();
#pragma unroll
        for (int k8 = 0; k8 < 32; k8 += 8) {
            unsigned a[2][4];
#pragma unroll
            for (int mt = 0; mt < 2; mt++) {
                int r = wm * 32 + mt * 16;
                a[mt][0] = sA[(r + gid    ) * 36 + k8 + tig    ];
                a[mt][1] = sA[(r + gid + 8) * 36 + k8 + tig    ];
                a[mt][2] = sA[(r + gid    ) * 36 + k8 + tig + 4];
                a[mt][3] = sA[(r + gid + 8) * 36 + k8 + tig + 4];
            }
#pragma unroll
            for (int nt = 0; nt < 8; nt++) {
                int n = wn * 64 + nt * 8 + gid;
                unsigned bb[2];
                bb[0] = sW[(k8 + tig    ) * 136 + n];
                bb[1] = sW[(k8 + tig + 4) * 136 + n];
                mma_tf32(acc[0][nt], a[0], bb);
                mma_tf32(acc[1][nt], a[1], bb);
            }
        }
        __syncthreads();
    }
#pragma unroll
    for (int mt = 0; mt < 2; mt++) {
#pragma unroll
        for (int nt = 0; nt < 8; nt++) {
            int col = col0 + wn * 64 + nt * 8 + tig * 2;
            float b0 = g_bc[col], b1 = g_bc[col + 1];
            int r0 = row0 + wm * 32 + mt * 16 + gid;
            if (r0 < M) {
                float2 o = make_float2(acc[mt][nt][0] + b0, acc[mt][nt][1] + b1);
                *(float2*)&g_qkvs[(size_t)r0 * N + col] = o;
            }
            if (r0 + 8 < M) {
                float2 o = make_float2(acc[mt][nt][2] + b0, acc[mt][nt][3] + b1);
                *(float2*)&g_qkvs[(size_t)(r0 + 8) * N + col] = o;
            }
        }
    }
}

// ------------------- K7: attention (R14 full-warp online softmax) + unflag -------------------
__global__ void __launch_bounds__(256) k_attn(float* __restrict__ out,
                                              const int* __restrict__ eids) {
    int b = blockIdx.x;
    if (b >= 2500) {
        int j = (b - 2500) * 256 + threadIdx.x;
        if (j < NE) g_flag[eids[j]] = 0;
        if (j == 0) g_ucount = 0;
        return;
    }
    int warp = threadIdx.x >> 5, lane = threadIdx.x & 31;
    int d = b * 8 + warp;
    if (d >= NN) return;
    int off0 = g_off[d], off1 = g_off[d + 1];

    float4 q4 = *(const float4*)&g_qkvs[(size_t)d * 512 + lane * 4];
    float m = -1e30f, den = 0.f;
    float4 acc = make_float4(0.f, 0.f, 0.f, 0.f);

    for (int i = off0; i < off1; i++) {
        int s = g_ss[i], u = g_su[i];
        float4 k4 = *(const float4*)&g_qkvs[(size_t)s * 512 + 128 + lane * 4];
        float4 e4 = *(const float4*)&g_Ec  [(size_t)u * H   +       lane * 4];
        float4 v4 = *(const float4*)&g_qkvs[(size_t)s * 512 + 256 + lane * 4];
        float p = q4.x * (k4.x + e4.x) + q4.y * (k4.y + e4.y)
                + q4.z * (k4.z + e4.z) + q4.w * (k4.w + e4.w);
#pragma unroll
        for (int o = 16; o; o >>= 1) p += __shfl_xor_sync(0xffffffffu, p, o);
        float a = p * 0.08838834764831845f;          // 1/sqrt(128)
        float mn = fmaxf(m, a);
        float scale = __expf(m - mn);
        float w = __expf(a - mn);
        den = den * scale + w;
        acc.x = acc.x * scale + w * (v4.x + e4.x);
        acc.y = acc.y * scale + w * (v4.y + e4.y);
        acc.z = acc.z * scale + w * (v4.z + e4.z);
        acc.w = acc.w * scale + w * (v4.w + e4.w);
        m = mn;
    }
    float rden = 1.f / fmaxf(den, 1e-16f);
    float4 sk = *(const float4*)&g_qkvs[(size_t)d * 512 + 384 + lane * 4];
    float4 o4 = make_float4(sk.x + acc.x * rden, sk.y + acc.y * rden,
                            sk.z + acc.z * rden, sk.w + acc.w * rden);
    *(float4*)&out[(size_t)d * H + lane * 4] = o4;
}

// ------------------- host -------------------
extern "C" void kernel_launch(void* const* d_in, const int* in_sizes, int n_in,
                              void* d_out, int out_size)
{
    const int*   event_type_ids = (const int*)  d_in[0];
    const int*   src_ids        = (const int*)  d_in[1];
    const float* src_mask       = (const float*)d_in[2];
    const int*   dst_ids        = (const int*)  d_in[3];
    const float* dst_mask       = (const float*)d_in[4];
    const int*   event_edge_ids = (const int*)  d_in[5];
    const float* event_emb      = (const float*)d_in[6];
    const float* event_mask     = (const float*)d_in[7];
    const float* event_ts       = (const float*)d_in[8];
    const int*   node_ids       = (const int*)  d_in[9];
    const int*   edge_ids       = (const int*)  d_in[10];
    const int*   edge_index     = (const int*)  d_in[11];
    const void*  timep          =               d_in[12];
    const float* memory         = (const float*)d_in[13];
    const float* last_update    = (const float*)d_in[14];
    const float* node_features  = (const float*)d_in[15];
    const float* edge_features  = (const float*)d_in[16];
    const float* time_w         = (const float*)d_in[17];
    const float* time_b         = (const float*)d_in[18];
    const float* gru_w_ih       = (const float*)d_in[19];
    const float* gru_w_hh       = (const float*)d_in[20];
    const float* gru_b_ih       = (const float*)d_in[21];
    const float* gru_b_hh       = (const float*)d_in[22];
    const float* wq             = (const float*)d_in[23];
    const float* bq             = (const float*)d_in[24];
    const float* wk             = (const float*)d_in[25];
    const float* bk             = (const float*)d_in[26];
    const float* wv             = (const float*)d_in[27];
    const float* bv             = (const float*)d_in[28];
    const float* we             = (const float*)d_in[29];
    const float* wskip          = (const float*)d_in[30];
    const float* bskip          = (const float*)d_in[31];
    float* out = (float*)d_out;

    // K1: prep (transposes, packw, flag, cnt0, zero, Hst build)
    k_prep<<<11057, 256>>>(gru_w_ih, gru_w_hh, we, wq, wk, wv, wskip,
                           bq, bk, bv, bskip, edge_ids, src_ids, dst_ids, memory);
    // K2: msg + hist + urelt
    k_phase2<<<6892, 256>>>(event_type_ids, src_ids, src_mask, dst_ids, dst_mask,
                            event_edge_ids, event_emb, event_mask, event_ts,
                            last_update, memory, time_w, time_b, edge_index, timep);
    // K3: scan
    k_scan<<<1, 512>>>();
    // K4: merged GRU GEMMs + E-GEMM + scatter + tag (independent work, one launch)
    k_mid<<<MID_TOT, 256>>>(gru_b_ih, gru_b_hh, src_ids, dst_ids,
                            edge_features, time_w, time_b, edge_index, edge_ids);
    // K5: gru activation
    k_act<<<(2 * EVT * H) / 256, 256>>>();
    // K6: q|k|v|skip GEMM with fused x gather
    k_qkvs_gemm<<<dim3((NN + 127) / 128, 4), 256>>>(node_ids, node_features, memory);
    // K7: attention (full-warp) + unflag
    k_attn<<<2500 + (NE + 255) / 256, 256>>>(out, edge_ids);
}

// round 17
// speedup vs baseline: 1.4800x; 1.3468x over previous
#include <cuda_runtime.h>
#include <math.h>

#define H      128
#define EVT    4096
#define NN     20000
#define NE     320000
#define MAXN   100000
#define MAXE   300000
#define MSG    640
#define DSTBIT (1 << 30)

// block-range layout for k_mid
#define GRU_BLKS   384
#define EG_BLKS    ((MAXE + 127) / 128)
#define SC_BLKS    ((NE + 255) / 256)
#define TAG_BLKS   32
#define MID_B1     GRU_BLKS
#define MID_B2     (MID_B1 + EG_BLKS)
#define MID_B3     (MID_B2 + SC_BLKS)
#define MID_TOT    (MID_B3 + TAG_BLKS)

// double-buffered smem geometry (words)
#define SA_WORDS   (128 * 36)
#define SW_WORDS   (32 * 136)
#define SMEM_WORDS (2 * SA_WORDS + 2 * SW_WORDS)
#define SMEM_BYTES (SMEM_WORDS * 4)      // 71680

// ------------------- device scratch (static, allowed) -------------------
__device__ float    g_aggS[MAXN * MSG];
__device__ float    g_aggD[MAXN * MSG];
__device__ float    g_cntS[MAXN];
__device__ float    g_cntD[MAXN];
__device__ float    g_Hst [2 * EVT * H];
__device__ float    g_GI  [2 * EVT * 384];
__device__ float    g_GH  [2 * EVT * 384];
__device__ float    g_newMem[2 * EVT * H];
__device__ int      g_tag [MAXN];
__device__ int      g_flag[MAXE];
__device__ int      g_list[MAXE];
__device__ int      g_slot[MAXE];
__device__ int      g_ucount;
__device__ float    g_urelt[MAXE];
__device__ float    g_Ec  [MAXE * H];
__device__ float    g_qkvs[NN * 512];
__device__ int      g_cnt [NN];
__device__ int      g_off [NN + 1];
__device__ int      g_cur [NN];
__device__ int      g_ss  [NE];
__device__ int      g_su  [NE];
__device__ float    g_wihT[640 * 384];
__device__ float    g_whhT[128 * 384];
__device__ float    g_weT [256 * 128];
__device__ float    g_wcT [128 * 512];
__device__ float    g_bc  [512];

// ------------------- helpers -------------------
__device__ __forceinline__ float get_time(const void* p) {
    int iv = *(const int*)p;
    if (iv > -1000000 && iv < 1000000) return (float)iv;
    return *(const float*)p;
}
__device__ __forceinline__ void cp16(unsigned* s, const void* g) {
    unsigned sa = (unsigned)__cvta_generic_to_shared(s);
    asm volatile("cp.async.ca.shared.global [%0], [%1], 16;" :: "r"(sa), "l"(g));
}
#define CP_COMMIT() asm volatile("cp.async.commit_group;" ::: "memory")
#define CP_WAIT0()  asm volatile("cp.async.wait_group 0;" ::: "memory")
// tf32 MMA: raw f32 registers; HW truncates mantissa to tf32.
__device__ __forceinline__ void mma_tf32(float* d, const unsigned* a, const unsigned* b) {
    asm("mma.sync.aligned.m16n8k8.row.col.f32.tf32.tf32.f32 "
        "{%0,%1,%2,%3}, {%4,%5,%6,%7}, {%8,%9}, {%0,%1,%2,%3};"
        : "+f"(d[0]), "+f"(d[1]), "+f"(d[2]), "+f"(d[3])
        : "r"(a[0]), "r"(a[1]), "r"(a[2]), "r"(a[3]), "r"(b[0]), "r"(b[1]));
}

// ------------------- K1: fused prep -------------------
__global__ void __launch_bounds__(256) k_prep(
    const float* __restrict__ gru_w_ih, const float* __restrict__ gru_w_hh,
    const float* __restrict__ we,
    const float* __restrict__ wq, const float* __restrict__ wk,
    const float* __restrict__ wv, const float* __restrict__ ws,
    const float* __restrict__ bq, const float* __restrict__ bk,
    const float* __restrict__ bv, const float* __restrict__ bs,
    const int* __restrict__ eids,
    const int* __restrict__ sids, const int* __restrict__ dids,
    const float* __restrict__ memory)
{
    int b = blockIdx.x, tid = threadIdx.x;
    if (b < 960) {
        int o = b * 256 + tid;
        int k = o / 384, n = o % 384;
        g_wihT[o] = gru_w_ih[n * 640 + k];
    } else if (b < 1152) {
        int o = (b - 960) * 256 + tid;
        int k = o / 384, n = o % 384;
        g_whhT[o] = gru_w_hh[n * 128 + k];
    } else if (b < 1280) {
        int o = (b - 1152) * 256 + tid;
        int k = o / 128, n = o % 128;
        g_weT[o] = we[n * 256 + k];
    } else if (b < 1536) {
        int o = (b - 1280) * 256 + tid;
        int k = o >> 9, n = o & 511;
        int grp = n >> 7, r = n & 127;
        const float* w = (grp == 0) ? wq : (grp == 1) ? wk : (grp == 2) ? wv : ws;
        g_wcT[o] = w[r * 128 + k];
        if (k == 0) {
            const float* bb = (grp == 0) ? bq : (grp == 1) ? bk : (grp == 2) ? bv : bs;
            g_bc[n] = bb[r];
        }
    } else if (b < 2786) {
        int j = (b - 1536) * 256 + tid;
        if (j < NE) {
            int e = eids[j];
            if (atomicExch(&g_flag[e], 1) == 0) {
                int u = atomicAdd(&g_ucount, 1);
                g_list[u] = e;
                g_slot[e] = u;
            }
        }
    } else if (b < 2865) {
        int i = (b - 2786) * 256 + tid;
        if (i < NN) g_cnt[i] = 0;
    } else if (b < 6961) {
        int i = b - 2865;
        int sid = sids[i], did = dids[i];
        for (int t = tid; t < MSG; t += 256) {
            g_aggS[sid * MSG + t] = 0.f;
            g_aggD[did * MSG + t] = 0.f;
        }
        if (tid == 0) { g_cntS[sid] = 0.f; g_cntD[did] = 0.f; }
    } else {
        int rr = (b - 6961) * 2 + (tid >> 7);
        int h = tid & 127;
        bool isS = rr < EVT;
        int i = isS ? rr : rr - EVT;
        int id = isS ? sids[i] : dids[i];
        g_Hst[rr * H + h] = memory[id * H + h];
    }
}

// ------------------- K2: msg + hist + urelt -------------------
__global__ void __launch_bounds__(256) k_phase2(
    const int* __restrict__ et, const int* __restrict__ sids,
    const float* __restrict__ smask, const int* __restrict__ dids,
    const float* __restrict__ dmask, const int* __restrict__ eids,
    const float* __restrict__ eemb, const float* __restrict__ emask,
    const float* __restrict__ ts, const float* __restrict__ last_update,
    const float* __restrict__ memory, const float* __restrict__ time_w,
    const float* __restrict__ time_b, const int* __restrict__ ei,
    const void* __restrict__ timep)
{
    int b = blockIdx.x, tid = threadIdx.x;
    if (b < 2048) {
        int i = b * 2 + (tid >> 7);
        int h = tid & 127;
        float em = emask[i], sm = smask[i], dm = dmask[i];
        int   etv = et[i];
        float tsv = ts[i];
        float el  = last_update[eids[i]];
        float rel = tsv - el * dm;
        float isn = (etv == 3 || etv == 4) ? 1.f : 0.f;
        float targ = tsv * isn + rel * dm;
        float cosv = __cosf(targ * time_w[h] + time_b[h]) * em;
        int sid = sids[i], did = dids[i];
        float sv = memory[sid * H + h] * sm;
        float dv = memory[did * H + h] * dm;
        float ev = eemb[i * H + h];
        float typ = (float)etv;
        float* aS = g_aggS + sid * MSG;
        atomicAdd(aS + 0 * H + h, typ  * em);
        atomicAdd(aS + 1 * H + h, sv   * em);
        atomicAdd(aS + 2 * H + h, dv   * em);
        atomicAdd(aS + 3 * H + h, cosv * em);
        atomicAdd(aS + 4 * H + h, ev   * em);
        float* aD = g_aggD + did * MSG;
        atomicAdd(aD + 0 * H + h, typ  * dm);
        atomicAdd(aD + 1 * H + h, dv   * dm);
        atomicAdd(aD + 2 * H + h, sv   * dm);
        atomicAdd(aD + 3 * H + h, cosv * dm);
        atomicAdd(aD + 4 * H + h, ev   * dm);
        if (h == 0) { atomicAdd(&g_cntS[sid], 1.f); atomicAdd(&g_cntD[did], 1.f); }
    } else if (b < 4548) {
        int j = (b - 2048) * 256 + tid;
        if (j < NE) atomicAdd(&g_cnt[ei[NE + j]], 1);
    } else {
        int u = (b - 4548) * 256 + tid;
        if (u < g_ucount)
            g_urelt[u] = get_time(timep) - last_update[g_list[u]];
    }
}

// ------------------- K3: single-block scan -------------------
__global__ void __launch_bounds__(512) k_scan() {
    __shared__ int ssum[512];
    int t = threadIdx.x;
    const int CH = 40;
    int base = t * CH;
    int loc = 0;
#pragma unroll 4
    for (int i = 0; i < CH; i++) {
        int idx = base + i;
        if (idx < NN) loc += g_cnt[idx];
    }
    ssum[t] = loc;
    __syncthreads();
    for (int off = 1; off < 512; off <<= 1) {
        int v = (t >= off) ? ssum[t - off] : 0;
        __syncthreads();
        ssum[t] += v;
        __syncthreads();
    }
    int run = ssum[t] - loc;
    for (int i = 0; i < CH; i++) {
        int idx = base + i;
        if (idx < NN) {
            g_off[idx] = run;
            g_cur[idx] = run;
            run += g_cnt[idx];
        }
    }
    if (t == 511) g_off[NN] = ssum[511];
}

// ------------------- shared MMA consume (reads one buffer) -------------------
__device__ __forceinline__ void gemm_consume(
    const unsigned* sA, const unsigned* sW, float acc[2][8][4],
    int wm, int wn, int gid, int tig)
{
#pragma unroll
    for (int k8 = 0; k8 < 32; k8 += 8) {
        unsigned a[2][4];
#pragma unroll
        for (int mt = 0; mt < 2; mt++) {
            int r = wm * 32 + mt * 16;
            a[mt][0] = sA[(r + gid    ) * 36 + k8 + tig    ];
            a[mt][1] = sA[(r + gid + 8) * 36 + k8 + tig    ];
            a[mt][2] = sA[(r + gid    ) * 36 + k8 + tig + 4];
            a[mt][3] = sA[(r + gid + 8) * 36 + k8 + tig + 4];
        }
#pragma unroll
        for (int nt = 0; nt < 8; nt++) {
            int n = wn * 64 + nt * 8 + gid;
            unsigned bb[2];
            bb[0] = sW[(k8 + tig    ) * 136 + n];
            bb[1] = sW[(k8 + tig + 4) * 136 + n];
            mma_tf32(acc[0][nt], a[0], bb);
            mma_tf32(acc[1][nt], a[1], bb);
        }
    }
}

// ------------------- K4: merged mid phase (pipelined GEMMs) -------------------
__global__ void __launch_bounds__(256, 2) k_mid(
    const float* __restrict__ b_ih, const float* __restrict__ b_hh,
    const int* __restrict__ sids, const int* __restrict__ dids,
    const float* __restrict__ EF, const float* __restrict__ tw,
    const float* __restrict__ tb,
    const int* __restrict__ ei, const int* __restrict__ eids)
{
    extern __shared__ unsigned dsm[];
    unsigned* sAb = dsm;
    unsigned* sWb = dsm + 2 * SA_WORDS;
    int b = blockIdx.x, tid = threadIdx.x;

    if (b >= MID_B2) {
        if (b < MID_B3) {                 // scatter
            int j = (b - MID_B2) * 256 + tid;
            if (j < NE) {
                int d = ei[NE + j];
                int pos = atomicAdd(&g_cur[d], 1);
                g_ss[pos] = ei[j];
                g_su[pos] = g_slot[eids[j]];
            }
        } else {                          // tag
            int t = (b - MID_B3) * 256 + tid;
            if (t < 2 * EVT) {
                bool isD = t >= EVT;
                int i = isD ? t - EVT : t;
                int id = isD ? dids[i] : sids[i];
                int key = (isD ? DSTBIT : 0) | (i + 1);
                atomicMax(&g_tag[id], key);
            }
        }
        return;
    }

    int lane = tid & 31, wid = tid >> 5;
    int wm = wid & 3, wn = wid >> 2;
    int gid = lane >> 2, tig = lane & 3;

    float acc[2][8][4];
#pragma unroll
    for (int mt = 0; mt < 2; mt++)
#pragma unroll
        for (int nt = 0; nt < 8; nt++)
#pragma unroll
            for (int c = 0; c < 4; c++) acc[mt][nt][c] = 0.f;

    if (b < MID_B1) {
        // ---------------- GRU GEMMs ----------------
        int bx = b & 63, by = (b >> 6) % 3, bz = b / 192;
        const float* WT   = bz ? g_whhT : g_wihT;
        const float* bias = bz ? b_hh   : b_ih;
        float*       C    = bz ? g_GH   : g_GI;
        int K = bz ? 128 : 640;
        int nch = K >> 5;
        const int N = 384;
        int row0 = bx * 128;
        int col0 = by * 128;
        bool isS = row0 < EVT;

        const float* aptr[4];
#pragma unroll
        for (int l = 0; l < 4; l++) {
            int row = (tid + l * 256) >> 3;
            int r = row0 + row;
            if (bz == 0) {
                int i = isS ? r : r - EVT;
                int id = isS ? sids[i] : dids[i];
                aptr[l] = (isS ? g_aggS : g_aggD) + (size_t)id * MSG;
            } else {
                aptr[l] = &g_Hst[(size_t)r * H];
            }
        }

        // stage chunk 0
        {
#pragma unroll
            for (int l = 0; l < 4; l++) {
                int idx = tid + l * 256;
                int row = idx >> 3, c4 = (idx & 7) * 4;
                cp16(&sAb[row * 36 + c4], aptr[l] + c4);
            }
#pragma unroll
            for (int l = 0; l < 4; l++) {
                int idx = tid + l * 256;
                int k = idx >> 5, n4 = (idx & 31) * 4;
                cp16(&sWb[k * 136 + n4], &WT[(size_t)k * N + col0 + n4]);
            }
            CP_COMMIT();
        }
        for (int ic = 0; ic < nch; ic++) {
            CP_WAIT0();
            __syncthreads();
            if (ic + 1 < nch) {
                int kc = (ic + 1) * 32;
                unsigned* sA = sAb + ((ic + 1) & 1) * SA_WORDS;
                unsigned* sW = sWb + ((ic + 1) & 1) * SW_WORDS;
#pragma unroll
                for (int l = 0; l < 4; l++) {
                    int idx = tid + l * 256;
                    int row = idx >> 3, c4 = (idx & 7) * 4;
                    cp16(&sA[row * 36 + c4], aptr[l] + kc + c4);
                }
#pragma unroll
                for (int l = 0; l < 4; l++) {
                    int idx = tid + l * 256;
                    int k = idx >> 5, n4 = (idx & 31) * 4;
                    cp16(&sW[k * 136 + n4], &WT[(size_t)(kc + k) * N + col0 + n4]);
                }
                CP_COMMIT();
            }
            gemm_consume(sAb + (ic & 1) * SA_WORDS, sWb + (ic & 1) * SW_WORDS,
                         acc, wm, wn, gid, tig);
            __syncthreads();
        }

        // epilogue: row scaling (agg mean) moved here for bz==0
        float inv[2][2] = {{1.f, 1.f}, {1.f, 1.f}};
        if (bz == 0) {
#pragma unroll
            for (int mt = 0; mt < 2; mt++)
#pragma unroll
                for (int hh = 0; hh < 2; hh++) {
                    int r = row0 + wm * 32 + mt * 16 + gid + hh * 8;
                    int i = isS ? r : r - EVT;
                    int id = isS ? sids[i] : dids[i];
                    float c = isS ? g_cntS[id] : g_cntD[id];
                    inv[mt][hh] = 1.f / fmaxf(c, 1.f);
                }
        }
#pragma unroll
        for (int mt = 0; mt < 2; mt++) {
#pragma unroll
            for (int nt = 0; nt < 8; nt++) {
                int col = col0 + wn * 64 + nt * 8 + tig * 2;
                float b0 = bias[col], b1 = bias[col + 1];
                int r0 = row0 + wm * 32 + mt * 16 + gid;
                float2 o0 = make_float2(acc[mt][nt][0] * inv[mt][0] + b0,
                                        acc[mt][nt][1] * inv[mt][0] + b1);
                float2 o1 = make_float2(acc[mt][nt][2] * inv[mt][1] + b0,
                                        acc[mt][nt][3] * inv[mt][1] + b1);
                *(float2*)&C[(size_t)r0 * 384 + col] = o0;
                *(float2*)&C[(size_t)(r0 + 8) * 384 + col] = o1;
            }
        }
    } else {
        // ---------------- E-GEMM ----------------
        int M = g_ucount;
        int row0 = (b - MID_B1) * 128;
        if (row0 >= M) return;

        // per-l row metadata
        float relt_l[4];
        const float* efp_l[4];
        bool ok_l[4];
#pragma unroll
        for (int l = 0; l < 4; l++) {
            int row = (tid + l * 256) >> 3;
            int r = row0 + row;
            ok_l[l] = (r < M);
            relt_l[l] = ok_l[l] ? g_urelt[r] : 0.f;
            efp_l[l] = ok_l[l] ? &EF[(size_t)g_list[r] * H] : EF;
        }

        // stage chunk ic into buffer buf: cols<128 computed cos (STS), else EF cp.async
        const int nch = 8;
        // chunk 0 (cos)
        {
#pragma unroll
            for (int l = 0; l < 4; l++) {
                int idx = tid + l * 256;
                int row = idx >> 3, c4 = (idx & 7) * 4;
                uint4 t = make_uint4(0u, 0u, 0u, 0u);
                if (ok_l[l]) {
                    float relt = relt_l[l];
                    t.x = __float_as_uint(__cosf(relt * tw[c4    ] + tb[c4    ]));
                    t.y = __float_as_uint(__cosf(relt * tw[c4 + 1] + tb[c4 + 1]));
                    t.z = __float_as_uint(__cosf(relt * tw[c4 + 2] + tb[c4 + 2]));
                    t.w = __float_as_uint(__cosf(relt * tw[c4 + 3] + tb[c4 + 3]));
                }
                *(uint4*)&sAb[row * 36 + c4] = t;
            }
#pragma unroll
            for (int l = 0; l < 4; l++) {
                int idx = tid + l * 256;
                int k = idx >> 5, n4 = (idx & 31) * 4;
                cp16(&sWb[k * 136 + n4], &g_weT[(size_t)k * 128 + n4]);
            }
            CP_COMMIT();
        }
        // NOTE: chunk-0 STS (cos) is made visible by the __syncthreads below.
        for (int ic = 0; ic < nch; ic++) {
            CP_WAIT0();
            __syncthreads();
            if (ic + 1 < nch) {
                int kc = (ic + 1) * 32;
                unsigned* sA = sAb + ((ic + 1) & 1) * SA_WORDS;
                unsigned* sW = sWb + ((ic + 1) & 1) * SW_WORDS;
                if (kc < 128) {
#pragma unroll
                    for (int l = 0; l < 4; l++) {
                        int idx = tid + l * 256;
                        int row = idx >> 3, c4 = (idx & 7) * 4;
                        int col = kc + c4;
                        uint4 t = make_uint4(0u, 0u, 0u, 0u);
                        if (ok_l[l]) {
                            float relt = relt_l[l];
                            t.x = __float_as_uint(__cosf(relt * tw[col    ] + tb[col    ]));
                            t.y = __float_as_uint(__cosf(relt * tw[col + 1] + tb[col + 1]));
                            t.z = __float_as_uint(__cosf(relt * tw[col + 2] + tb[col + 2]));
                            t.w = __float_as_uint(__cosf(relt * tw[col + 3] + tb[col + 3]));
                        }
                        *(uint4*)&sA[row * 36 + c4] = t;
                    }
                } else {
#pragma unroll
                    for (int l = 0; l < 4; l++) {
                        int idx = tid + l * 256;
                        int row = idx >> 3, c4 = (idx & 7) * 4;
                        if (ok_l[l]) {
                            cp16(&sA[row * 36 + c4], efp_l[l] + kc - 128 + c4);
                        } else {
                            *(uint4*)&sA[row * 36 + c4] = make_uint4(0u, 0u, 0u, 0u);
                        }
                    }
                }
#pragma unroll
                for (int l = 0; l < 4; l++) {
                    int idx = tid + l * 256;
                    int k = idx >> 5, n4 = (idx & 31) * 4;
                    cp16(&sW[k * 136 + n4], &g_weT[(size_t)(kc + k) * 128 + n4]);
                }
                CP_COMMIT();
            }
            gemm_consume(sAb + (ic & 1) * SA_WORDS, sWb + (ic & 1) * SW_WORDS,
                         acc, wm, wn, gid, tig);
            __syncthreads();
        }
#pragma unroll
        for (int mt = 0; mt < 2; mt++) {
#pragma unroll
            for (int nt = 0; nt < 8; nt++) {
                int col = wn * 64 + nt * 8 + tig * 2;
                int r0 = row0 + wm * 32 + mt * 16 + gid;
                if (r0 < M) {
                    float2 o = make_float2(acc[mt][nt][0], acc[mt][nt][1]);
                    *(float2*)&g_Ec[(size_t)r0 * 128 + col] = o;
                }
                if (r0 + 8 < M) {
                    float2 o = make_float2(acc[mt][nt][2], acc[mt][nt][3]);
                    *(float2*)&g_Ec[(size_t)(r0 + 8) * 128 + col] = o;
                }
            }
        }
    }
}

// ------------------- K5: gru_act -------------------
__global__ void __launch_bounds__(256) k_act() {
    int idx = blockIdx.x * 256 + threadIdx.x;
    int r = idx >> 7, h = idx & 127;
    float ir = g_GI[r * 384 + h];
    float iz = g_GI[r * 384 + 128 + h];
    float in_ = g_GI[r * 384 + 256 + h];
    float hr = g_GH[r * 384 + h];
    float hz = g_GH[r * 384 + 128 + h];
    float hn = g_GH[r * 384 + 256 + h];
    float rr = 1.f / (1.f + expf(-(ir + hr)));
    float zz = 1.f / (1.f + expf(-(iz + hz)));
    float nn = tanhf(in_ + rr * hn);
    g_newMem[idx] = (1.f - zz) * nn + zz * g_Hst[idx];
}

// ------------------- K6: q|k|v|skip GEMM (pipelined W; STS A) -------------------
__global__ void __launch_bounds__(256, 2) k_qkvs_gemm(
    const int* __restrict__ node_ids, const float* __restrict__ NF,
    const float* __restrict__ memory)
{
    extern __shared__ unsigned dsm[];
    unsigned* sAb = dsm;
    unsigned* sWb = dsm + 2 * SA_WORDS;
    const int M = NN, N = 512;
    int row0 = blockIdx.x * 128;
    int col0 = blockIdx.y * 128;
    int tid = threadIdx.x, lane = tid & 31, wid = tid >> 5;
    int wm = wid & 3, wn = wid >> 2;
    int gid = lane >> 2, tig = lane & 3;

    // per-l row metadata for x gather
    const float* nfp[4];
    const float* mp[4];
    bool ok_l[4];
#pragma unroll
    for (int l = 0; l < 4; l++) {
        int row = (tid + l * 256) >> 3;
        int r = row0 + row;
        ok_l[l] = (r < M);
        int nid = ok_l[l] ? node_ids[r] : 0;
        nfp[l] = &NF[(size_t)nid * H];
        int tg = g_tag[nid];
        if (tg == 0)          mp[l] = &memory[(size_t)nid * H];
        else if (tg & DSTBIT) mp[l] = &g_newMem[(size_t)(EVT + (tg & ~DSTBIT) - 1) * H];
        else                  mp[l] = &g_newMem[(size_t)(tg - 1) * H];
    }

    float acc[2][8][4];
#pragma unroll
    for (int mt = 0; mt < 2; mt++)
#pragma unroll
        for (int nt = 0; nt < 8; nt++)
#pragma unroll
            for (int c = 0; c < 4; c++) acc[mt][nt][c] = 0.f;

    const int nch = 4;   // K=128
    // stage chunk 0
    {
#pragma unroll
        for (int l = 0; l < 4; l++) {
            int idx = tid + l * 256;
            int row = idx >> 3, c4 = (idx & 7) * 4;
            uint4 t = make_uint4(0u, 0u, 0u, 0u);
            if (ok_l[l]) {
                float4 nf = *(const float4*)(nfp[l] + c4);
                float4 mv = *(const float4*)(mp[l] + c4);
                t.x = __float_as_uint(nf.x + mv.x);
                t.y = __float_as_uint(nf.y + mv.y);
                t.z = __float_as_uint(nf.z + mv.z);
                t.w = __float_as_uint(nf.w + mv.w);
            }
            *(uint4*)&sAb[row * 36 + c4] = t;
        }
#pragma unroll
        for (int l = 0; l < 4; l++) {
            int idx = tid + l * 256;
            int k = idx >> 5, n4 = (idx & 31) * 4;
            cp16(&sWb[k * 136 + n4], &g_wcT[(size_t)k * N + col0 + n4]);
        }
        CP_COMMIT();
    }
    for (int ic = 0; ic < nch; ic++) {
        CP_WAIT0();
        __syncthreads();
        if (ic + 1 < nch) {
            int kc = (ic + 1) * 32;
            unsigned* sA = sAb + ((ic + 1) & 1) * SA_WORDS;
            unsigned* sW = sWb + ((ic + 1) & 1) * SW_WORDS;
#pragma unroll
            for (int l = 0; l < 4; l++) {
                int idx = tid + l * 256;
                int row = idx >> 3, c4 = (idx & 7) * 4;
                uint4 t = make_uint4(0u, 0u, 0u, 0u);
                if (ok_l[l]) {
                    float4 nf = *(const float4*)(nfp[l] + kc + c4);
                    float4 mv = *(const float4*)(mp[l] + kc + c4);
                    t.x = __float_as_uint(nf.x + mv.x);
                    t.y = __float_as_uint(nf.y + mv.y);
                    t.z = __float_as_uint(nf.z + mv.z);
                    t.w = __float_as_uint(nf.w + mv.w);
                }
                *(uint4*)&sA[row * 36 + c4] = t;
            }
#pragma unroll
            for (int l = 0; l < 4; l++) {
                int idx = tid + l * 256;
                int k = idx >> 5, n4 = (idx & 31) * 4;
                cp16(&sW[k * 136 + n4], &g_wcT[(size_t)(kc + k) * N + col0 + n4]);
            }
            CP_COMMIT();
        }
        gemm_consume(sAb + (ic & 1) * SA_WORDS, sWb + (ic & 1) * SW_WORDS,
                     acc, wm, wn, gid, tig);
        __syncthreads();
    }
#pragma unroll
    for (int mt = 0; mt < 2; mt++) {
#pragma unroll
        for (int nt = 0; nt < 8; nt++) {
            int col = col0 + wn * 64 + nt * 8 + tig * 2;
            float b0 = g_bc[col], b1 = g_bc[col + 1];
            int r0 = row0 + wm * 32 + mt * 16 + gid;
            if (r0 < M) {
                float2 o = make_float2(acc[mt][nt][0] + b0, acc[mt][nt][1] + b1);
                *(float2*)&g_qkvs[(size_t)r0 * N + col] = o;
            }
            if (r0 + 8 < M) {
                float2 o = make_float2(acc[mt][nt][2] + b0, acc[mt][nt][3] + b1);
                *(float2*)&g_qkvs[(size_t)(r0 + 8) * N + col] = o;
            }
        }
    }
}

// ------------------- K7: attention (R14 full-warp) + unflag -------------------
__global__ void __launch_bounds__(256) k_attn(float* __restrict__ out,
                                              const int* __restrict__ eids) {
    int b = blockIdx.x;
    if (b >= 2500) {
        int j = (b - 2500) * 256 + threadIdx.x;
        if (j < NE) g_flag[eids[j]] = 0;
        if (j == 0) g_ucount = 0;
        return;
    }
    int warp = threadIdx.x >> 5, lane = threadIdx.x & 31;
    int d = b * 8 + warp;
    if (d >= NN) return;
    int off0 = g_off[d], off1 = g_off[d + 1];

    float4 q4 = *(const float4*)&g_qkvs[(size_t)d * 512 + lane * 4];
    float m = -1e30f, den = 0.f;
    float4 acc = make_float4(0.f, 0.f, 0.f, 0.f);

    for (int i = off0; i < off1; i++) {
        int s = g_ss[i], u = g_su[i];
        float4 k4 = *(const float4*)&g_qkvs[(size_t)s * 512 + 128 + lane * 4];
        float4 e4 = *(const float4*)&g_Ec  [(size_t)u * H   +       lane * 4];
        float4 v4 = *(const float4*)&g_qkvs[(size_t)s * 512 + 256 + lane * 4];
        float p = q4.x * (k4.x + e4.x) + q4.y * (k4.y + e4.y)
                + q4.z * (k4.z + e4.z) + q4.w * (k4.w + e4.w);
#pragma unroll
        for (int o = 16; o; o >>= 1) p += __shfl_xor_sync(0xffffffffu, p, o);
        float a = p * 0.08838834764831845f;
        float mn = fmaxf(m, a);
        float scale = __expf(m - mn);
        float w = __expf(a - mn);
        den = den * scale + w;
        acc.x = acc.x * scale + w * (v4.x + e4.x);
        acc.y = acc.y * scale + w * (v4.y + e4.y);
        acc.z = acc.z * scale + w * (v4.z + e4.z);
        acc.w = acc.w * scale + w * (v4.w + e4.w);
        m = mn;
    }
    float rden = 1.f / fmaxf(den, 1e-16f);
    float4 sk = *(const float4*)&g_qkvs[(size_t)d * 512 + 384 + lane * 4];
    float4 o4 = make_float4(sk.x + acc.x * rden, sk.y + acc.y * rden,
                            sk.z + acc.z * rden, sk.w + acc.w * rden);
    *(float4*)&out[(size_t)d * H + lane * 4] = o4;
}

// ------------------- host -------------------
extern "C" void kernel_launch(void* const* d_in, const int* in_sizes, int n_in,
                              void* d_out, int out_size)
{
    const int*   event_type_ids = (const int*)  d_in[0];
    const int*   src_ids        = (const int*)  d_in[1];
    const float* src_mask       = (const float*)d_in[2];
    const int*   dst_ids        = (const int*)  d_in[3];
    const float* dst_mask       = (const float*)d_in[4];
    const int*   event_edge_ids = (const int*)  d_in[5];
    const float* event_emb      = (const float*)d_in[6];
    const float* event_mask     = (const float*)d_in[7];
    const float* event_ts       = (const float*)d_in[8];
    const int*   node_ids       = (const int*)  d_in[9];
    const int*   edge_ids       = (const int*)  d_in[10];
    const int*   edge_index     = (const int*)  d_in[11];
    const void*  timep          =               d_in[12];
    const float* memory         = (const float*)d_in[13];
    const float* last_update    = (const float*)d_in[14];
    const float* node_features  = (const float*)d_in[15];
    const float* edge_features  = (const float*)d_in[16];
    const float* time_w         = (const float*)d_in[17];
    const float* time_b         = (const float*)d_in[18];
    const float* gru_w_ih       = (const float*)d_in[19];
    const float* gru_w_hh       = (const float*)d_in[20];
    const float* gru_b_ih       = (const float*)d_in[21];
    const float* gru_b_hh       = (const float*)d_in[22];
    const float* wq             = (const float*)d_in[23];
    const float* bq             = (const float*)d_in[24];
    const float* wk             = (const float*)d_in[25];
    const float* bk             = (const float*)d_in[26];
    const float* wv             = (const float*)d_in[27];
    const float* bv             = (const float*)d_in[28];
    const float* we             = (const float*)d_in[29];
    const float* wskip          = (const float*)d_in[30];
    const float* bskip          = (const float*)d_in[31];
    float* out = (float*)d_out;

    static bool attr_done = false;
    if (!attr_done) {
        cudaFuncSetAttribute(k_mid, cudaFuncAttributeMaxDynamicSharedMemorySize, SMEM_BYTES);
        cudaFuncSetAttribute(k_qkvs_gemm, cudaFuncAttributeMaxDynamicSharedMemorySize, SMEM_BYTES);
        attr_done = true;
    }

    // K1: prep
    k_prep<<<11057, 256>>>(gru_w_ih, gru_w_hh, we, wq, wk, wv, wskip,
                           bq, bk, bv, bskip, edge_ids, src_ids, dst_ids, memory);
    // K2: msg + hist + urelt
    k_phase2<<<6892, 256>>>(event_type_ids, src_ids, src_mask, dst_ids, dst_mask,
                            event_edge_ids, event_emb, event_mask, event_ts,
                            last_update, memory, time_w, time_b, edge_index, timep);
    // K3: scan
    k_scan<<<1, 512>>>();
    // K4: merged pipelined GEMMs + scatter + tag
    k_mid<<<MID_TOT, 256, SMEM_BYTES>>>(gru_b_ih, gru_b_hh, src_ids, dst_ids,
                                        edge_features, time_w, time_b,
                                        edge_index, edge_ids);
    // K5: gru activation
    k_act<<<(2 * EVT * H) / 256, 256>>>();
    // K6: q|k|v|skip GEMM with fused x gather (pipelined W)
    k_qkvs_gemm<<<dim3((NN + 127) / 128, 4), 256, SMEM_BYTES>>>(node_ids, node_features, memory);
    // K7: attention + unflag
    k_attn<<<2500 + (NE + 255) / 256, 256>>>(out, edge_ids);
}